// round 11
// baseline (speedup 1.0000x reference)
#include <cuda_runtime.h>
#include <cstdint>

#define NN 50000
#define NE 800000
#define NG 64
#define HID 300
#define HID2 600
#define NLAYER 5
#define EPSV 1e-5f

// ---------------- scratch (static __device__, no allocs) ----------------
__device__ float g_hraw[(size_t)NN * HID];
__device__ float g_agg [(size_t)NN * HID];
__device__ float g_t   [(size_t)NN * HID2];
__device__ int   g_deg [NN];
__device__ int   g_rowptr[NN + 1];
__device__ int   g_cursor[NN];
__device__ int   g_srcs[NE];
__device__ float g_ews [NE];
__device__ float g_sum1[HID2], g_sq1[HID2], g_a1[HID2], g_c1[HID2];
__device__ float g_sum2[HID],  g_sq2[HID],  g_a2[HID],  g_c2[HID];

// ---------------- packed f32x2 helpers ----------------
__device__ __forceinline__ void ffma2(unsigned long long& d,
                                      unsigned long long a, unsigned long long b) {
    asm("fma.rn.f32x2 %0, %1, %2, %0;" : "+l"(d) : "l"(a), "l"(b));
}
__device__ __forceinline__ unsigned long long dup_f32(float v) {
    unsigned long long r;
    asm("mov.b64 %0, {%1, %1};" : "=l"(r) : "r"(__float_as_uint(v)));
    return r;
}
__device__ __forceinline__ void unpack2(unsigned long long p, float& lo, float& hi) {
    uint32_t l, h;
    asm("mov.b64 {%0, %1}, %2;" : "=r"(l), "=r"(h) : "l"(p));
    lo = __uint_as_float(l);
    hi = __uint_as_float(h);
}

// ---------------- small utility kernels ----------------
__global__ void k_zero_f(float* p, int n) {
    int i = blockIdx.x * blockDim.x + threadIdx.x;
    if (i < n) p[i] = 0.f;
}
__global__ void k_zero_deg() {
    int i = blockIdx.x * blockDim.x + threadIdx.x;
    if (i < NN) g_deg[i] = 0;
}
__global__ void k_count(const int* __restrict__ dst) {
    int e = blockIdx.x * blockDim.x + threadIdx.x;
    if (e < NE) atomicAdd(&g_deg[dst[e]], 1);
}
// single-block exclusive scan of g_deg -> g_rowptr, g_cursor
__global__ void k_scan() {
    __shared__ int sh[1024];
    int offset = 0;
    for (int base = 0; base < NN; base += 1024) {
        int i = base + threadIdx.x;
        int v = (i < NN) ? g_deg[i] : 0;
        sh[threadIdx.x] = v;
        __syncthreads();
        #pragma unroll
        for (int d = 1; d < 1024; d <<= 1) {
            int t = (threadIdx.x >= d) ? sh[threadIdx.x - d] : 0;
            __syncthreads();
            sh[threadIdx.x] += t;
            __syncthreads();
        }
        int incl = sh[threadIdx.x];
        if (i < NN) {
            g_rowptr[i] = offset + incl - v;
            g_cursor[i] = offset + incl - v;
        }
        offset += sh[1023];
        __syncthreads();
    }
    if (threadIdx.x == 0) g_rowptr[NN] = offset;
}
__global__ void k_scatter(const int* __restrict__ src, const int* __restrict__ dst,
                          const float* __restrict__ ea) {
    int e = blockIdx.x * blockDim.x + threadIdx.x;
    if (e < NE) {
        int d = dst[e];
        int p = atomicAdd(&g_cursor[d], 1);
        g_srcs[p] = src[e];
        g_ews[p]  = ea[e];
    }
}

// ---------------- SpMM: agg[n] = sum_e ew * f(h[src]) ----------------
template <bool TRANS>
__global__ void k_spmm(const float* __restrict__ hraw,
                       const float* __restrict__ a, const float* __restrict__ c) {
    int n = blockIdx.x;
    int f = threadIdx.x;
    int beg = g_rowptr[n], end = g_rowptr[n + 1];
    if (f >= HID) return;
    float af = 0.f, cf = 0.f;
    if (TRANS) { af = a[f]; cf = c[f]; }
    float acc = 0.f;
    for (int e = beg; e < end; e++) {
        int s  = g_srcs[e];
        float w = g_ews[e];
        float v = __ldg(hraw + (size_t)s * HID + f);
        if (TRANS) v = fmaxf(fmaf(af, v, cf), 0.f);
        acc = fmaf(w, v, acc);
    }
    g_agg[(size_t)n * HID + f] = acc;
}

// ---------------- tiled fp32 GEMM, FFMA2 core, 256x128 tile ----------------
// C = f(A) @ B + bias, fused BN stats.
// A: [M,K] row-major, B: [K,N] row-major. K,N are multiples of 4.
// TRANS_A: f(v) = relu(ta[k]*v + tc[k]); else identity.
// STATS: accumulate per-column sum / sumsq of C (rows < M only).
#define BM 256
#define BN 128
#define BK 8
template <bool TRANS_A, bool STATS>
__global__ __launch_bounds__(256, 1)
void k_gemm(const float* __restrict__ A, const float* __restrict__ B,
            const float* __restrict__ bias,
            const float* __restrict__ ta, const float* __restrict__ tc,
            float* __restrict__ C, int M, int N, int K,
            float* __restrict__ sum_out, float* __restrict__ sq_out) {
    __shared__ __align__(16) float As[2][BK][BM + 2];
    __shared__ __align__(16) float Bs[2][BK][BN];
    __shared__ float red[16][BN];

    const int tid = threadIdx.x;
    const int tx = tid & 15, ty = tid >> 4;
    const int m0 = blockIdx.y * BM, n0 = blockIdx.x * BN;

    const int arow = tid;                 // 0..255
    const bool rowv = (m0 + arow) < M;
    const float* Arow = A + (size_t)(m0 + arow) * K;
    const int bk = tid >> 5;              // 0..7
    const int bn = (tid & 31) * 4;        // 0..124
    const bool colv = (n0 + bn) < N;      // N%4==0 -> vector-granular

    // packed accumulators: acc2[i2][j] holds rows (ty*16+2*i2, +1), col tx*8+j
    unsigned long long acc2[8][8];
    #pragma unroll
    for (int i = 0; i < 8; i++)
        #pragma unroll
        for (int j = 0; j < 8; j++) acc2[i][j] = 0ull;

    const int nK = (K + BK - 1) / BK;

    float4 pa0, pa1, pb;
    auto load_tile = [&](int kt) {
        pa0 = make_float4(0.f, 0.f, 0.f, 0.f);
        pa1 = pa0;
        pb  = pa0;
        if (rowv) {
            if (kt + 3 < K) {
                pa0 = *(const float4*)(Arow + kt);
                if (TRANS_A) {
                    float4 a4 = *(const float4*)(ta + kt);
                    float4 c4 = *(const float4*)(tc + kt);
                    pa0.x = fmaxf(fmaf(a4.x, pa0.x, c4.x), 0.f);
                    pa0.y = fmaxf(fmaf(a4.y, pa0.y, c4.y), 0.f);
                    pa0.z = fmaxf(fmaf(a4.z, pa0.z, c4.z), 0.f);
                    pa0.w = fmaxf(fmaf(a4.w, pa0.w, c4.w), 0.f);
                }
            }
            if (kt + 7 < K) {
                pa1 = *(const float4*)(Arow + kt + 4);
                if (TRANS_A) {
                    float4 a4 = *(const float4*)(ta + kt + 4);
                    float4 c4 = *(const float4*)(tc + kt + 4);
                    pa1.x = fmaxf(fmaf(a4.x, pa1.x, c4.x), 0.f);
                    pa1.y = fmaxf(fmaf(a4.y, pa1.y, c4.y), 0.f);
                    pa1.z = fmaxf(fmaf(a4.z, pa1.z, c4.z), 0.f);
                    pa1.w = fmaxf(fmaf(a4.w, pa1.w, c4.w), 0.f);
                }
            }
        }
        int gk = kt + bk;
        if (gk < K && colv)
            pb = *(const float4*)(B + (size_t)gk * N + n0 + bn);
    };
    auto store_tile = [&](int s) {
        As[s][0][arow] = pa0.x;
        As[s][1][arow] = pa0.y;
        As[s][2][arow] = pa0.z;
        As[s][3][arow] = pa0.w;
        As[s][4][arow] = pa1.x;
        As[s][5][arow] = pa1.y;
        As[s][6][arow] = pa1.z;
        As[s][7][arow] = pa1.w;
        *(float4*)&Bs[s][bk][bn] = pb;
    };

    // prologue
    load_tile(0);
    store_tile(0);
    __syncthreads();

    for (int t = 0; t < nK; t++) {
        const int cur = t & 1;
        const bool more = (t + 1 < nK);
        if (more) load_tile((t + 1) * BK);

        #pragma unroll
        for (int kk = 0; kk < BK; kk++) {
            unsigned long long a2[8];
            #pragma unroll
            for (int i = 0; i < 8; i++)
                a2[i] = *(const unsigned long long*)&As[cur][kk][ty * 16 + 2 * i];
            float4 b0 = *(const float4*)&Bs[cur][kk][tx * 8];
            float4 b1 = *(const float4*)&Bs[cur][kk][tx * 8 + 4];
            unsigned long long bd[8];
            bd[0] = dup_f32(b0.x); bd[1] = dup_f32(b0.y);
            bd[2] = dup_f32(b0.z); bd[3] = dup_f32(b0.w);
            bd[4] = dup_f32(b1.x); bd[5] = dup_f32(b1.y);
            bd[6] = dup_f32(b1.z); bd[7] = dup_f32(b1.w);
            #pragma unroll
            for (int i = 0; i < 8; i++)
                #pragma unroll
                for (int j = 0; j < 8; j++)
                    ffma2(acc2[i][j], a2[i], bd[j]);
        }

        if (more) {
            store_tile((t + 1) & 1);
            __syncthreads();
        }
    }

    // bias
    float bv[8];
    #pragma unroll
    for (int j = 0; j < 8; j++) {
        int col = n0 + tx * 8 + j;
        bv[j] = (col < N) ? bias[col] : 0.f;
    }

    float s[8], q[8];
    #pragma unroll
    for (int j = 0; j < 8; j++) { s[j] = 0.f; q[j] = 0.f; }

    // unpack per M-pair: bias, store, stats
    #pragma unroll
    for (int i2 = 0; i2 < 8; i2++) {
        float lo[8], hi[8];
        #pragma unroll
        for (int j = 0; j < 8; j++) {
            unpack2(acc2[i2][j], lo[j], hi[j]);
            lo[j] += bv[j];
            hi[j] += bv[j];
        }
        int r0 = m0 + ty * 16 + 2 * i2;
        int r1 = r0 + 1;
        int colb = n0 + tx * 8;
        if (r0 < M) {
            if (colb < N)
                *(float4*)(C + (size_t)r0 * N + colb) =
                    make_float4(lo[0], lo[1], lo[2], lo[3]);
            if (colb + 4 < N)
                *(float4*)(C + (size_t)r0 * N + colb + 4) =
                    make_float4(lo[4], lo[5], lo[6], lo[7]);
            if (STATS)
                #pragma unroll
                for (int j = 0; j < 8; j++) {
                    s[j] += lo[j];
                    q[j] = fmaf(lo[j], lo[j], q[j]);
                }
        }
        if (r1 < M) {
            if (colb < N)
                *(float4*)(C + (size_t)r1 * N + colb) =
                    make_float4(hi[0], hi[1], hi[2], hi[3]);
            if (colb + 4 < N)
                *(float4*)(C + (size_t)r1 * N + colb + 4) =
                    make_float4(hi[4], hi[5], hi[6], hi[7]);
            if (STATS)
                #pragma unroll
                for (int j = 0; j < 8; j++) {
                    s[j] += hi[j];
                    q[j] = fmaf(hi[j], hi[j], q[j]);
                }
        }
    }

    if (STATS) {
        __syncthreads();
        #pragma unroll
        for (int j = 0; j < 8; j++) red[ty][tx * 8 + j] = s[j];
        __syncthreads();
        if (tid < BN) {
            float t = 0.f;
            #pragma unroll
            for (int r = 0; r < 16; r++) t += red[r][tid];
            int col = n0 + tid;
            if (col < N) atomicAdd(&sum_out[col], t);
        }
        __syncthreads();
        #pragma unroll
        for (int j = 0; j < 8; j++) red[ty][tx * 8 + j] = q[j];
        __syncthreads();
        if (tid < BN) {
            float t = 0.f;
            #pragma unroll
            for (int r = 0; r < 16; r++) t += red[r][tid];
            int col = n0 + tid;
            if (col < N) atomicAdd(&sq_out[col], t);
        }
    }
}

// ---------------- BN finalize: a = g*rstd, c = beta - mean*a ----------------
__global__ void k_finalize(const float* __restrict__ sum, const float* __restrict__ sq,
                           const float* __restrict__ gam, const float* __restrict__ bet,
                           float* __restrict__ a, float* __restrict__ c, int n) {
    int i = blockIdx.x * blockDim.x + threadIdx.x;
    if (i < n) {
        float m   = sum[i] * (1.f / NN);
        float var = sq[i] * (1.f / NN) - m * m;
        float r   = rsqrtf(var + EPSV);
        float av  = gam[i] * r;
        a[i] = av;
        c[i] = bet[i] - m * av;
    }
}

// ---------------- final output: h = a2*hraw + c2 (no relu), pool by batch ----------------
__global__ void k_output(const int* __restrict__ batch,
                         float* __restrict__ out_h, float* __restrict__ out_pool) {
    int idx = blockIdx.x * blockDim.x + threadIdx.x;
    if (idx < NN * HID) {
        int n = idx / HID;
        int f = idx - n * HID;
        float v = fmaf(g_a2[f], g_hraw[idx], g_c2[f]);
        out_h[idx] = v;
        atomicAdd(&out_pool[(size_t)batch[n] * HID + f], v);
    }
}

// ---------------- host driver ----------------
extern "C" void kernel_launch(void* const* d_in, const int* in_sizes, int n_in,
                              void* d_out, int out_size) {
    const int*   batch = (const int*)  d_in[0];
    const float* x     = (const float*)d_in[1];
    const int*   ei    = (const int*)  d_in[2];   // [2, NE]: src then dst
    const float* ea    = (const float*)d_in[3];
    const float* linW  = (const float*)d_in[4];
    const float* linb  = (const float*)d_in[5];
    const float* W1s   = (const float*)d_in[6];
    const float* b1s   = (const float*)d_in[7];
    const float* g1s   = (const float*)d_in[8];
    const float* be1s  = (const float*)d_in[9];
    const float* W2s   = (const float*)d_in[10];
    const float* b2s   = (const float*)d_in[11];
    const float* gos   = (const float*)d_in[12];
    const float* bos   = (const float*)d_in[13];

    float* out      = (float*)d_out;
    float* out_h    = out;
    float* out_pool = out + (size_t)NN * HID;

    const int* src = ei;
    const int* dst = ei + NE;

    float *p_hraw, *p_agg, *p_t;
    float *p_sum1, *p_sq1, *p_a1, *p_c1, *p_sum2, *p_sq2, *p_a2, *p_c2;
    cudaGetSymbolAddress((void**)&p_hraw, g_hraw);
    cudaGetSymbolAddress((void**)&p_agg,  g_agg);
    cudaGetSymbolAddress((void**)&p_t,    g_t);
    cudaGetSymbolAddress((void**)&p_sum1, g_sum1);
    cudaGetSymbolAddress((void**)&p_sq1,  g_sq1);
    cudaGetSymbolAddress((void**)&p_a1,   g_a1);
    cudaGetSymbolAddress((void**)&p_c1,   g_c1);
    cudaGetSymbolAddress((void**)&p_sum2, g_sum2);
    cudaGetSymbolAddress((void**)&p_sq2,  g_sq2);
    cudaGetSymbolAddress((void**)&p_a2,   g_a2);
    cudaGetSymbolAddress((void**)&p_c2,   g_c2);

    const int EB = (NE + 255) / 256;

    // ---- CSR build ----
    k_zero_deg<<<(NN + 255) / 256, 256>>>();
    k_count<<<EB, 256>>>(dst);
    k_scan<<<1, 1024>>>();
    k_scatter<<<EB, 256>>>(src, dst, ea);

    // ---- h0 = x @ linW + linb (K=20) ----
    {
        dim3 grid((HID + BN - 1) / BN, (NN + BM - 1) / BM);
        k_gemm<false, false><<<grid, 256>>>(x, linW, linb, nullptr, nullptr,
                                            p_hraw, NN, HID, 2 * 10, nullptr, nullptr);
    }

    dim3 grid1((HID2 + BN - 1) / BN, (NN + BM - 1) / BM);  // 5 x 196
    dim3 grid2((HID  + BN - 1) / BN, (NN + BM - 1) / BM);  // 3 x 196

    for (int i = 0; i < NLAYER; i++) {
        // message passing + segment sum (input transform = previous layer BN+relu)
        if (i == 0)
            k_spmm<false><<<NN, 320>>>(p_hraw, nullptr, nullptr);
        else
            k_spmm<true><<<NN, 320>>>(p_hraw, p_a2, p_c2);

        // GEMM1 + fused stats
        k_zero_f<<<(HID2 + 255) / 256, 256>>>(p_sum1, HID2);
        k_zero_f<<<(HID2 + 255) / 256, 256>>>(p_sq1, HID2);
        k_gemm<false, true><<<grid1, 256>>>(p_agg, W1s + (size_t)i * HID * HID2,
                                            b1s + (size_t)i * HID2, nullptr, nullptr,
                                            p_t, NN, HID2, HID, p_sum1, p_sq1);
        k_finalize<<<(HID2 + 255) / 256, 256>>>(p_sum1, p_sq1,
                                                g1s + (size_t)i * HID2, be1s + (size_t)i * HID2,
                                                p_a1, p_c1, HID2);

        // GEMM2 with fused relu(bn1) on A-load, + fused stats
        k_zero_f<<<(HID + 255) / 256, 256>>>(p_sum2, HID);
        k_zero_f<<<(HID + 255) / 256, 256>>>(p_sq2, HID);
        k_gemm<true, true><<<grid2, 256>>>(p_t, W2s + (size_t)i * HID2 * HID,
                                           b2s + (size_t)i * HID, p_a1, p_c1,
                                           p_hraw, NN, HID, HID2, p_sum2, p_sq2);
        k_finalize<<<(HID + 255) / 256, 256>>>(p_sum2, p_sq2,
                                               gos + (size_t)i * HID, bos + (size_t)i * HID,
                                               p_a2, p_c2, HID);
    }

    // ---- output: h (bn, no relu) and xpool ----
    k_zero_f<<<(NG * HID + 255) / 256, 256>>>(out_pool, NG * HID);
    k_output<<<((NN * HID) + 255) / 256, 256>>>(batch, out_h, out_pool);
}

// round 14
// speedup vs baseline: 1.0281x; 1.0281x over previous
#include <cuda_runtime.h>
#include <cstdint>

#define NN 50000
#define NE 800000
#define NG 64
#define HID 300
#define HID2 600
#define NLAYER 5
#define EPSV 1e-5f

// ---------------- scratch (static __device__, no allocs) ----------------
__device__ float g_hraw[(size_t)NN * HID];
__device__ float g_agg [(size_t)NN * HID];
__device__ float g_t   [(size_t)NN * HID2];
__device__ int   g_deg [NN];
__device__ int   g_rowptr[NN + 1];
__device__ int   g_cursor[NN];
__device__ int   g_srcs[NE];
__device__ float g_ews [NE];
__device__ float g_sum1[HID2], g_sq1[HID2], g_a1[HID2], g_c1[HID2];
__device__ float g_sum2[HID],  g_sq2[HID],  g_a2[HID],  g_c2[HID];

// ---------------- packed f32x2 helpers ----------------
__device__ __forceinline__ void ffma2(unsigned long long& d,
                                      unsigned long long a, unsigned long long b) {
    asm("fma.rn.f32x2 %0, %1, %2, %0;" : "+l"(d) : "l"(a), "l"(b));
}
__device__ __forceinline__ unsigned long long dup_f32(float v) {
    unsigned long long r;
    asm("mov.b64 %0, {%1, %1};" : "=l"(r) : "r"(__float_as_uint(v)));
    return r;
}
__device__ __forceinline__ void unpack2(unsigned long long p, float& lo, float& hi) {
    uint32_t l, h;
    asm("mov.b64 {%0, %1}, %2;" : "=r"(l), "=r"(h) : "l"(p));
    lo = __uint_as_float(l);
    hi = __uint_as_float(h);
}

// ---------------- small utility kernels ----------------
__global__ void k_zero_f(float* p, int n) {
    int i = blockIdx.x * blockDim.x + threadIdx.x;
    if (i < n) p[i] = 0.f;
}
__global__ void k_zero_deg() {
    int i = blockIdx.x * blockDim.x + threadIdx.x;
    if (i < NN) g_deg[i] = 0;
}
__global__ void k_count(const int* __restrict__ dst) {
    int e = blockIdx.x * blockDim.x + threadIdx.x;
    if (e < NE) atomicAdd(&g_deg[dst[e]], 1);
}
// single-block exclusive scan of g_deg -> g_rowptr, g_cursor
__global__ void k_scan() {
    __shared__ int sh[1024];
    int offset = 0;
    for (int base = 0; base < NN; base += 1024) {
        int i = base + threadIdx.x;
        int v = (i < NN) ? g_deg[i] : 0;
        sh[threadIdx.x] = v;
        __syncthreads();
        #pragma unroll
        for (int d = 1; d < 1024; d <<= 1) {
            int t = (threadIdx.x >= d) ? sh[threadIdx.x - d] : 0;
            __syncthreads();
            sh[threadIdx.x] += t;
            __syncthreads();
        }
        int incl = sh[threadIdx.x];
        if (i < NN) {
            g_rowptr[i] = offset + incl - v;
            g_cursor[i] = offset + incl - v;
        }
        offset += sh[1023];
        __syncthreads();
    }
    if (threadIdx.x == 0) g_rowptr[NN] = offset;
}
__global__ void k_scatter(const int* __restrict__ src, const int* __restrict__ dst,
                          const float* __restrict__ ea) {
    int e = blockIdx.x * blockDim.x + threadIdx.x;
    if (e < NE) {
        int d = dst[e];
        int p = atomicAdd(&g_cursor[d], 1);
        g_srcs[p] = src[e];
        g_ews[p]  = ea[e];
    }
}

// ---------------- SpMM: agg[n] = sum_e ew * f(h[src]) ----------------
template <bool TRANS>
__global__ void k_spmm(const float* __restrict__ hraw,
                       const float* __restrict__ a, const float* __restrict__ c) {
    int n = blockIdx.x;
    int f = threadIdx.x;
    int beg = g_rowptr[n], end = g_rowptr[n + 1];
    if (f >= HID) return;
    float af = 0.f, cf = 0.f;
    if (TRANS) { af = a[f]; cf = c[f]; }
    float acc = 0.f;
    for (int e = beg; e < end; e++) {
        int s  = g_srcs[e];
        float w = g_ews[e];
        float v = __ldg(hraw + (size_t)s * HID + f);
        if (TRANS) v = fmaxf(fmaf(af, v, cf), 0.f);
        acc = fmaf(w, v, acc);
    }
    g_agg[(size_t)n * HID + f] = acc;
}

// ---------------- tiled fp32 GEMM, FFMA2 core, 128x128 tile, double-buffered ----------------
// C = f(A) @ B + bias, fused BN stats.
// A: [M,K] row-major, B: [K,N] row-major. K,N multiples of 4.
// TRANS_A: f(v) = relu(ta[k]*v + tc[k]); else identity.
// STATS: accumulate per-column sum / sumsq of C (rows < M only).
#define BM 128
#define BN 128
#define BK 8
template <bool TRANS_A, bool STATS>
__global__ __launch_bounds__(256, 2)
void k_gemm(const float* __restrict__ A, const float* __restrict__ B,
            const float* __restrict__ bias,
            const float* __restrict__ ta, const float* __restrict__ tc,
            float* __restrict__ C, int M, int N, int K,
            float* __restrict__ sum_out, float* __restrict__ sq_out) {
    __shared__ __align__(16) float As[2][BK][BM + 4];
    __shared__ __align__(16) float Bs[2][BK][BN];
    __shared__ float red[16][BN];

    const int tid = threadIdx.x;
    const int tx = tid & 15, ty = tid >> 4;
    const int m0 = blockIdx.y * BM, n0 = blockIdx.x * BN;

    const int arow = tid >> 1;          // 0..127
    const int ak   = (tid & 1) * 4;     // 0 or 4
    const bool rowv = (m0 + arow) < M;
    const float* Arow = A + (size_t)(m0 + arow) * K;
    const int bk = tid >> 5;            // 0..7
    const int bn = (tid & 31) * 4;      // 0..124
    const bool colv = (n0 + bn) < N;    // N%4==0 -> vector-granular

    // packed accumulators: acc2[i2][j] holds rows (ty*8+2*i2, +1), col tx*8+j
    unsigned long long acc2[4][8];
    #pragma unroll
    for (int i = 0; i < 4; i++)
        #pragma unroll
        for (int j = 0; j < 8; j++) acc2[i][j] = 0ull;

    const int nK = (K + BK - 1) / BK;

    float4 pa, pb;
    auto load_tile = [&](int kt) {
        pa = make_float4(0.f, 0.f, 0.f, 0.f);
        pb = pa;
        int gka = kt + ak;
        if (rowv && gka + 3 < K) {
            pa = *(const float4*)(Arow + gka);
            if (TRANS_A) {
                float4 a4 = *(const float4*)(ta + gka);
                float4 c4 = *(const float4*)(tc + gka);
                pa.x = fmaxf(fmaf(a4.x, pa.x, c4.x), 0.f);
                pa.y = fmaxf(fmaf(a4.y, pa.y, c4.y), 0.f);
                pa.z = fmaxf(fmaf(a4.z, pa.z, c4.z), 0.f);
                pa.w = fmaxf(fmaf(a4.w, pa.w, c4.w), 0.f);
            }
        }
        int gkb = kt + bk;
        if (gkb < K && colv)
            pb = *(const float4*)(B + (size_t)gkb * N + n0 + bn);
    };
    auto store_tile = [&](int s) {
        As[s][ak + 0][arow] = pa.x;
        As[s][ak + 1][arow] = pa.y;
        As[s][ak + 2][arow] = pa.z;
        As[s][ak + 3][arow] = pa.w;
        *(float4*)&Bs[s][bk][bn] = pb;
    };

    // prologue
    load_tile(0);
    store_tile(0);
    __syncthreads();

    for (int t = 0; t < nK; t++) {
        const int cur = t & 1;
        const bool more = (t + 1 < nK);
        if (more) load_tile((t + 1) * BK);

        #pragma unroll
        for (int kk = 0; kk < BK; kk++) {
            unsigned long long a2[4];
            #pragma unroll
            for (int i = 0; i < 4; i++)
                a2[i] = *(const unsigned long long*)&As[cur][kk][ty * 8 + 2 * i];
            float4 b0 = *(const float4*)&Bs[cur][kk][tx * 8];
            float4 b1 = *(const float4*)&Bs[cur][kk][tx * 8 + 4];
            unsigned long long bd[8];
            bd[0] = dup_f32(b0.x); bd[1] = dup_f32(b0.y);
            bd[2] = dup_f32(b0.z); bd[3] = dup_f32(b0.w);
            bd[4] = dup_f32(b1.x); bd[5] = dup_f32(b1.y);
            bd[6] = dup_f32(b1.z); bd[7] = dup_f32(b1.w);
            #pragma unroll
            for (int i = 0; i < 4; i++)
                #pragma unroll
                for (int j = 0; j < 8; j++)
                    ffma2(acc2[i][j], a2[i], bd[j]);
        }

        if (more) {
            store_tile((t + 1) & 1);
            __syncthreads();
        }
    }

    // bias
    float bv[8];
    #pragma unroll
    for (int j = 0; j < 8; j++) {
        int col = n0 + tx * 8 + j;
        bv[j] = (col < N) ? bias[col] : 0.f;
    }

    float s[8], q[8];
    #pragma unroll
    for (int j = 0; j < 8; j++) { s[j] = 0.f; q[j] = 0.f; }

    // unpack per M-pair: bias, store, stats
    #pragma unroll
    for (int i2 = 0; i2 < 4; i2++) {
        float lo[8], hi[8];
        #pragma unroll
        for (int j = 0; j < 8; j++) {
            unpack2(acc2[i2][j], lo[j], hi[j]);
            lo[j] += bv[j];
            hi[j] += bv[j];
        }
        int r0 = m0 + ty * 8 + 2 * i2;
        int r1 = r0 + 1;
        int colb = n0 + tx * 8;
        if (r0 < M) {
            if (colb < N)
                *(float4*)(C + (size_t)r0 * N + colb) =
                    make_float4(lo[0], lo[1], lo[2], lo[3]);
            if (colb + 4 < N)
                *(float4*)(C + (size_t)r0 * N + colb + 4) =
                    make_float4(lo[4], lo[5], lo[6], lo[7]);
            if (STATS)
                #pragma unroll
                for (int j = 0; j < 8; j++) {
                    s[j] += lo[j];
                    q[j] = fmaf(lo[j], lo[j], q[j]);
                }
        }
        if (r1 < M) {
            if (colb < N)
                *(float4*)(C + (size_t)r1 * N + colb) =
                    make_float4(hi[0], hi[1], hi[2], hi[3]);
            if (colb + 4 < N)
                *(float4*)(C + (size_t)r1 * N + colb + 4) =
                    make_float4(hi[4], hi[5], hi[6], hi[7]);
            if (STATS)
                #pragma unroll
                for (int j = 0; j < 8; j++) {
                    s[j] += hi[j];
                    q[j] = fmaf(hi[j], hi[j], q[j]);
                }
        }
    }

    if (STATS) {
        __syncthreads();
        #pragma unroll
        for (int j = 0; j < 8; j++) red[ty][tx * 8 + j] = s[j];
        __syncthreads();
        if (tid < BN) {
            float t = 0.f;
            #pragma unroll
            for (int r = 0; r < 16; r++) t += red[r][tid];
            int col = n0 + tid;
            if (col < N) atomicAdd(&sum_out[col], t);
        }
        __syncthreads();
        #pragma unroll
        for (int j = 0; j < 8; j++) red[ty][tx * 8 + j] = q[j];
        __syncthreads();
        if (tid < BN) {
            float t = 0.f;
            #pragma unroll
            for (int r = 0; r < 16; r++) t += red[r][tid];
            int col = n0 + tid;
            if (col < N) atomicAdd(&sq_out[col], t);
        }
    }
}

// ---------------- BN finalize: a = g*rstd, c = beta - mean*a ----------------
__global__ void k_finalize(const float* __restrict__ sum, const float* __restrict__ sq,
                           const float* __restrict__ gam, const float* __restrict__ bet,
                           float* __restrict__ a, float* __restrict__ c, int n) {
    int i = blockIdx.x * blockDim.x + threadIdx.x;
    if (i < n) {
        float m   = sum[i] * (1.f / NN);
        float var = sq[i] * (1.f / NN) - m * m;
        float r   = rsqrtf(var + EPSV);
        float av  = gam[i] * r;
        a[i] = av;
        c[i] = bet[i] - m * av;
    }
}

// ---------------- final output: h = a2*hraw + c2 (no relu), pool by batch ----------------
__global__ void k_output(const int* __restrict__ batch,
                         float* __restrict__ out_h, float* __restrict__ out_pool) {
    int idx = blockIdx.x * blockDim.x + threadIdx.x;
    if (idx < NN * HID) {
        int n = idx / HID;
        int f = idx - n * HID;
        float v = fmaf(g_a2[f], g_hraw[idx], g_c2[f]);
        out_h[idx] = v;
        atomicAdd(&out_pool[(size_t)batch[n] * HID + f], v);
    }
}

// ---------------- host driver ----------------
extern "C" void kernel_launch(void* const* d_in, const int* in_sizes, int n_in,
                              void* d_out, int out_size) {
    const int*   batch = (const int*)  d_in[0];
    const float* x     = (const float*)d_in[1];
    const int*   ei    = (const int*)  d_in[2];   // [2, NE]: src then dst
    const float* ea    = (const float*)d_in[3];
    const float* linW  = (const float*)d_in[4];
    const float* linb  = (const float*)d_in[5];
    const float* W1s   = (const float*)d_in[6];
    const float* b1s   = (const float*)d_in[7];
    const float* g1s   = (const float*)d_in[8];
    const float* be1s  = (const float*)d_in[9];
    const float* W2s   = (const float*)d_in[10];
    const float* b2s   = (const float*)d_in[11];
    const float* gos   = (const float*)d_in[12];
    const float* bos   = (const float*)d_in[13];

    float* out      = (float*)d_out;
    float* out_h    = out;
    float* out_pool = out + (size_t)NN * HID;

    const int* src = ei;
    const int* dst = ei + NE;

    float *p_hraw, *p_agg, *p_t;
    float *p_sum1, *p_sq1, *p_a1, *p_c1, *p_sum2, *p_sq2, *p_a2, *p_c2;
    cudaGetSymbolAddress((void**)&p_hraw, g_hraw);
    cudaGetSymbolAddress((void**)&p_agg,  g_agg);
    cudaGetSymbolAddress((void**)&p_t,    g_t);
    cudaGetSymbolAddress((void**)&p_sum1, g_sum1);
    cudaGetSymbolAddress((void**)&p_sq1,  g_sq1);
    cudaGetSymbolAddress((void**)&p_a1,   g_a1);
    cudaGetSymbolAddress((void**)&p_c1,   g_c1);
    cudaGetSymbolAddress((void**)&p_sum2, g_sum2);
    cudaGetSymbolAddress((void**)&p_sq2,  g_sq2);
    cudaGetSymbolAddress((void**)&p_a2,   g_a2);
    cudaGetSymbolAddress((void**)&p_c2,   g_c2);

    const int EB = (NE + 255) / 256;

    // ---- CSR build ----
    k_zero_deg<<<(NN + 255) / 256, 256>>>();
    k_count<<<EB, 256>>>(dst);
    k_scan<<<1, 1024>>>();
    k_scatter<<<EB, 256>>>(src, dst, ea);

    // ---- h0 = x @ linW + linb (K=20) ----
    {
        dim3 grid((HID + BN - 1) / BN, (NN + BM - 1) / BM);
        k_gemm<false, false><<<grid, 256>>>(x, linW, linb, nullptr, nullptr,
                                            p_hraw, NN, HID, 2 * 10, nullptr, nullptr);
    }

    dim3 grid1((HID2 + BN - 1) / BN, (NN + BM - 1) / BM);  // 5 x 391
    dim3 grid2((HID  + BN - 1) / BN, (NN + BM - 1) / BM);  // 3 x 391

    for (int i = 0; i < NLAYER; i++) {
        // message passing + segment sum (input transform = previous layer BN+relu)
        if (i == 0)
            k_spmm<false><<<NN, 320>>>(p_hraw, nullptr, nullptr);
        else
            k_spmm<true><<<NN, 320>>>(p_hraw, p_a2, p_c2);

        // GEMM1 + fused stats
        k_zero_f<<<(HID2 + 255) / 256, 256>>>(p_sum1, HID2);
        k_zero_f<<<(HID2 + 255) / 256, 256>>>(p_sq1, HID2);
        k_gemm<false, true><<<grid1, 256>>>(p_agg, W1s + (size_t)i * HID * HID2,
                                            b1s + (size_t)i * HID2, nullptr, nullptr,
                                            p_t, NN, HID2, HID, p_sum1, p_sq1);
        k_finalize<<<(HID2 + 255) / 256, 256>>>(p_sum1, p_sq1,
                                                g1s + (size_t)i * HID2, be1s + (size_t)i * HID2,
                                                p_a1, p_c1, HID2);

        // GEMM2 with fused relu(bn1) on A-load, + fused stats
        k_zero_f<<<(HID + 255) / 256, 256>>>(p_sum2, HID);
        k_zero_f<<<(HID + 255) / 256, 256>>>(p_sq2, HID);
        k_gemm<true, true><<<grid2, 256>>>(p_t, W2s + (size_t)i * HID2 * HID,
                                           b2s + (size_t)i * HID, p_a1, p_c1,
                                           p_hraw, NN, HID, HID2, p_sum2, p_sq2);
        k_finalize<<<(HID + 255) / 256, 256>>>(p_sum2, p_sq2,
                                               gos + (size_t)i * HID, bos + (size_t)i * HID,
                                               p_a2, p_c2, HID);
    }

    // ---- output: h (bn, no relu) and xpool ----
    k_zero_f<<<(NG * HID + 255) / 256, 256>>>(out_pool, NG * HID);
    k_output<<<((NN * HID) + 255) / 256, 256>>>(batch, out_h, out_pool);
}